// round 11
// baseline (speedup 1.0000x reference)
#include <cuda_runtime.h>
#include <cuda_bf16.h>
#include <cstdint>
#include <cstddef>

typedef unsigned long long ull;

#define BATCH 4096
#define DIN   8192
#define DOUT  8192
#define KIN   64
#define KOUT  64
#define NF    65     // rfft bins of 128

// ---------------- scratch (static device globals; no allocation) -------------
__device__ float g_Xre[NF][BATCH * KIN];             // [f][b*64+j]
__device__ float g_Xim[NF][BATCH * KIN];
__device__ float g_Wre[NF][KIN * KOUT];              // [f][j*64+o] = Re conj(fft W)
__device__ float g_Wim[NF][KIN * KOUT];              // [f][j*64+o] = Im conj(fft W)
__device__ float g_Y[(size_t)BATCH * NF * KOUT * 2]; // [b][f][o][re,im]
// B tiles, plain row-major [n][k] bf16 hi/lo per frequency (128x128 each)
__device__ __align__(16) __nv_bfloat16 g_Bhi[NF][128 * 128];
__device__ __align__(16) __nv_bfloat16 g_Blo[NF][128 * 128];

__device__ __forceinline__ uint32_t smem_to_u32(const void* p) {
    uint32_t a;
    asm("{ .reg .u64 t; cvta.to.shared.u64 t, %1; cvt.u32.u64 %0, t; }"
        : "=r"(a) : "l"(p));
    return a;
}
#define LDMATRIX_X4(r0, r1, r2, r3, addr) \
    asm volatile("ldmatrix.sync.aligned.m8n8.x4.shared.b16 {%0,%1,%2,%3}, [%4];" \
        : "=r"(r0), "=r"(r1), "=r"(r2), "=r"(r3) : "r"(addr))
// NOTE: non-volatile — pure register op, data deps preserve correctness,
// lets ptxas schedule HMMAs under subsequent ldmatrix latency.
#define MMA_BF16(c, a, b) \
    asm("mma.sync.aligned.m16n8k16.row.col.f32.bf16.bf16.f32 " \
        "{%0,%1,%2,%3}, {%4,%5,%6,%7}, {%8,%9}, {%0,%1,%2,%3};" \
        : "+f"((c)[0]), "+f"((c)[1]), "+f"((c)[2]), "+f"((c)[3]) \
        : "r"((a)[0]), "r"((a)[1]), "r"((a)[2]), "r"((a)[3]), \
          "r"((b)[0]), "r"((b)[1]))

// ---------------- warp-level 128-pt radix-2 DIF FFT --------------------------
__device__ __forceinline__ void fft128(float xr[4], float xi[4],
                                       const float* __restrict__ twc,
                                       const float* __restrict__ tws,
                                       int lane) {
#pragma unroll
    for (int r = 0; r < 2; r++) {
        int i = r * 32 + lane;
        float ar = xr[r], ai = xi[r], br = xr[r + 2], bi = xi[r + 2];
        xr[r] = ar + br; xi[r] = ai + bi;
        float dr = ar - br, di = ai - bi;
        float c = twc[i], s = tws[i];
        xr[r + 2] = dr * c - di * s;
        xi[r + 2] = dr * s + di * c;
    }
    {
        float c = twc[2 * lane], s = tws[2 * lane];
#pragma unroll
        for (int p = 0; p < 2; p++) {
            int a = 2 * p, bq = 2 * p + 1;
            float ar = xr[a], ai = xi[a], br = xr[bq], bi = xi[bq];
            xr[a] = ar + br; xi[a] = ai + bi;
            float dr = ar - br, di = ai - bi;
            xr[bq] = dr * c - di * s;
            xi[bq] = dr * s + di * c;
        }
    }
#pragma unroll
    for (int h = 16; h >= 1; h >>= 1) {
        int m = (lane & (h - 1)) * (64 / h);
        float c = twc[m], s = tws[m];
        bool upper = (lane & h) != 0;
#pragma unroll
        for (int r = 0; r < 4; r++) {
            float pr = __shfl_xor_sync(0xffffffffu, xr[r], h);
            float pi = __shfl_xor_sync(0xffffffffu, xi[r], h);
            float ur = upper ? pr : xr[r];
            float ui = upper ? pi : xi[r];
            float vr = upper ? xr[r] : pr;
            float vi = upper ? xi[r] : pi;
            if (!upper) { xr[r] = ur + vr; xi[r] = ui + vi; }
            else {
                float dr = ur - vr, di = ui - vi;
                xr[r] = dr * c - di * s;
                xi[r] = dr * s + di * c;
            }
        }
    }
}

// ---------------- K0: conj(FFT) of weight first-rows -------------------------
__global__ void wfft_kernel(const float* __restrict__ W) {
    __shared__ float sw[128];
    __shared__ float tc[128];
    __shared__ float ts[128];
    int oj = blockIdx.x;
    int t = threadIdx.x;
    sw[t] = W[oj * 128 + t];
    float ang = 6.2831853071795864769f * (float)t / 128.0f;  // +sin => conj
    tc[t] = cosf(ang);
    ts[t] = sinf(ang);
    __syncthreads();
    if (t < NF) {
        float ar = 0.f, ai = 0.f;
#pragma unroll 8
        for (int u = 0; u < 128; u++) {
            int p = (t * u) & 127;
            ar = fmaf(sw[u], tc[p], ar);
            ai = fmaf(sw[u], ts[p], ai);
        }
        int o = oj >> 6, j = oj & 63;
        g_Wre[t][j * 64 + o] = ar;
        g_Wim[t][j * 64 + o] = ai;
    }
}

// ---------------- K0b: build B tiles (bf16 hi/lo, row-major [n][k]) ----------
// B[n][k]: n<64 -> Yr rows (o=n): k<64 -> Wr[j=k][o], else -Wi[j][o]
//          n>=64 -> Yi rows:      k<64 -> Wi[j][o],   else  Wr[j][o]
__global__ void bprep_kernel() {
    int f = blockIdx.x;
    for (int i = threadIdx.x; i < 128 * 128; i += blockDim.x) {
        int n = i >> 7, k = i & 127;
        int o = n & 63, j = k & 63;
        float wr = g_Wre[f][j * 64 + o];
        float wi = g_Wim[f][j * 64 + o];
        float v = (n < 64) ? ((k < 64) ? wr : -wi)
                           : ((k < 64) ? wi :  wr);
        __nv_bfloat16 h = __float2bfloat16(v);
        float lo = v - __bfloat162float(h);
        g_Bhi[f][i] = h;
        g_Blo[f][i] = __float2bfloat16(lo);
    }
}

// ---------------- K1: FFT of x blocks, 2 real blocks per complex FFT ----------
__global__ void __launch_bounds__(512) xfft_kernel(const float* __restrict__ x,
                                                   const float* __restrict__ D) {
    extern __shared__ float sm[];
    float* sZr = sm;                 // [128][33]
    float* sZi = sZr + 128 * 33;
    float* twc = sZi + 128 * 33;
    float* tws = twc + 64;
    int b = blockIdx.x, tid = threadIdx.x;
    if (tid < 64) {
        float ang = -6.2831853071795864769f * (float)tid / 128.0f;
        twc[tid] = cosf(ang);
        tws[tid] = sinf(ang);
    }
    __syncthreads();
    int warp = tid >> 5, lane = tid & 31;
    const float* xb = x + (size_t)b * DIN;
    for (int pp = 0; pp < 2; pp++) {
        int p = warp * 2 + pp;
        float xr[4], xi[4];
#pragma unroll
        for (int r = 0; r < 4; r++) {
            int n = r * 32 + lane;
            int iu = (2 * p) * 128 + n;
            int iv = iu + 128;
            xr[r] = xb[iu] * D[iu];
            xi[r] = xb[iv] * D[iv];
        }
        fft128(xr, xi, twc, tws, lane);
#pragma unroll
        for (int r = 0; r < 4; r++) {
            int n = r * 32 + lane;
            sZr[n * 33 + p] = xr[r];
            sZi[n * 33 + p] = xi[r];
        }
    }
    __syncthreads();
    for (int i = tid; i < NF * KIN; i += 512) {
        int f = i >> 6, j = i & 63;
        int p = j >> 1, v = j & 1;
        int g = (128 - f) & 127;
        int sf = __brev((unsigned)f) >> 25;
        int sg = __brev((unsigned)g) >> 25;
        float zr1 = sZr[sf * 33 + p], zi1 = sZi[sf * 33 + p];
        float zr2 = sZr[sg * 33 + p], zi2 = sZi[sg * 33 + p];
        float outr, outi;
        if (v == 0) { outr = 0.5f * (zr1 + zr2); outi = 0.5f * (zi1 - zi2); }
        else        { outr = 0.5f * (zi1 + zi2); outi = 0.5f * (zr2 - zr1); }
        g_Xre[f][b * 64 + j] = outr;
        g_Xim[f][b * 64 + j] = outi;
    }
}

// ---------------- K2: per-frequency GEMM via mma.sync bf16 split-2 ------------
// CTA = (64-row b-tile, one frequency), 256 threads = 8 warps (2M x 4N).
// Warp tile 32x32. Mainloop software-pipelined: iter it+1's ldmatrix issued
// before iter it's MMAs (double-buffered fragments) so LDS latency hides
// under HMMA issue. 2 CTAs/SM (smem 104.4KB).
// SMEM (272B pitch = conflict-free ldmatrix):
//   Ah @0, Al @17408, Bh @34816, Bl @69632   (total 104448 B)
__global__ void __launch_bounds__(256, 2) cgemm_mma_kernel() {
    extern __shared__ char smem[];
    const int PITCH = 272;
    const uint32_t AL = 17408, BH = 34816, BL = 69632;
    int f = blockIdx.y, bt = blockIdx.x, tid = threadIdx.x;

    // --- stage A: load X fp32 (64 rows), split to bf16 hi/lo ---
    {
        const float2* xr2 = (const float2*)(g_Xre[f] + (size_t)bt * 4096);
        const float2* xi2 = (const float2*)(g_Xim[f] + (size_t)bt * 4096);
        for (int idx = tid; idx < 64 * 32; idx += 256) {
            int m = idx >> 5, kp = idx & 31;
            float2 vr = xr2[idx];
            float2 vi = xi2[idx];
            __nv_bfloat16 h0 = __float2bfloat16(vr.x);
            __nv_bfloat16 h1 = __float2bfloat16(vr.y);
            uint32_t hp = (uint32_t)__bfloat16_as_ushort(h0) |
                          ((uint32_t)__bfloat16_as_ushort(h1) << 16);
            __nv_bfloat16 l0 = __float2bfloat16(vr.x - __bfloat162float(h0));
            __nv_bfloat16 l1 = __float2bfloat16(vr.y - __bfloat162float(h1));
            uint32_t lp = (uint32_t)__bfloat16_as_ushort(l0) |
                          ((uint32_t)__bfloat16_as_ushort(l1) << 16);
            *(uint32_t*)(smem + m * PITCH + kp * 4) = hp;
            *(uint32_t*)(smem + AL + m * PITCH + kp * 4) = lp;
            h0 = __float2bfloat16(vi.x);
            h1 = __float2bfloat16(vi.y);
            hp = (uint32_t)__bfloat16_as_ushort(h0) |
                 ((uint32_t)__bfloat16_as_ushort(h1) << 16);
            l0 = __float2bfloat16(vi.x - __bfloat162float(h0));
            l1 = __float2bfloat16(vi.y - __bfloat162float(h1));
            lp = (uint32_t)__bfloat16_as_ushort(l0) |
                 ((uint32_t)__bfloat16_as_ushort(l1) << 16);
            *(uint32_t*)(smem + m * PITCH + 128 + kp * 4) = hp;
            *(uint32_t*)(smem + AL + m * PITCH + 128 + kp * 4) = lp;
        }
    }
    // --- stage B: copy precomputed tiles into pitched smem ---
    {
        const uint4* bh = (const uint4*)g_Bhi[f];
        const uint4* bl = (const uint4*)g_Blo[f];
        for (int idx = tid; idx < 2048; idx += 256) {
            int n = idx >> 4, c = idx & 15;
            *(uint4*)(smem + BH + n * PITCH + c * 16) = bh[idx];
            *(uint4*)(smem + BL + n * PITCH + c * 16) = bl[idx];
        }
    }
    __syncthreads();

    uint32_t sA = smem_to_u32(smem);
    int lane = tid & 31, wid = tid >> 5;
    int wm = wid >> 2, wn = wid & 3;          // warp tile: M 32 x N 32
    int r = lane & 7, ti = lane >> 3;

    // ldmatrix lane base addresses
    uint32_t aBase = sA + (uint32_t)((wm * 32 + r + 8 * (ti & 1)) * PITCH
                                     + (ti >> 1) * 16);
    uint32_t bBase0 = sA + BH + (uint32_t)((wn * 32 + r + 8 * (ti >> 1)) * PITCH
                                           + (ti & 1) * 16);
    uint32_t bBase1 = bBase0 + 16 * PITCH;

    float acc[2][4][4];
#pragma unroll
    for (int mt = 0; mt < 2; mt++)
#pragma unroll
        for (int nt = 0; nt < 4; nt++)
#pragma unroll
            for (int q = 0; q < 4; q++) acc[mt][nt][q] = 0.f;

    // merged loop: it = s*8 + ks, s in {0:Ah*Bh, 1:Ah*Bl, 2:Al*Bh}
    uint32_t af[2][2][4];
    uint32_t bf[2][4][2];
#define LOAD_FRAGS(buf, it_) do {                                              \
        const int s_ = (it_) >> 3;                                             \
        const uint32_t aO = (s_ == 2) ? AL : 0;                                \
        const uint32_t bO = (s_ == 1) ? (BL - BH) : 0;                         \
        const uint32_t ka = ((it_) & 7) * 32;                                  \
        LDMATRIX_X4(af[buf][0][0], af[buf][0][1], af[buf][0][2], af[buf][0][3],\
                    aBase + aO + ka);                                          \
        LDMATRIX_X4(af[buf][1][0], af[buf][1][1], af[buf][1][2], af[buf][1][3],\
                    aBase + aO + 16 * PITCH + ka);                             \
        LDMATRIX_X4(bf[buf][0][0], bf[buf][0][1], bf[buf][1][0], bf[buf][1][1],\
                    bBase0 + bO + ka);                                         \
        LDMATRIX_X4(bf[buf][2][0], bf[buf][2][1], bf[buf][3][0], bf[buf][3][1],\
                    bBase1 + bO + ka);                                         \
    } while (0)

    LOAD_FRAGS(0, 0);
#pragma unroll
    for (int it = 0; it < 24; it++) {
        const int cur = it & 1;
        if (it + 1 < 24) LOAD_FRAGS(cur ^ 1, it + 1);
#pragma unroll
        for (int mt = 0; mt < 2; mt++)
#pragma unroll
            for (int nt = 0; nt < 4; nt++)
                MMA_BF16(acc[mt][nt], af[cur][mt], bf[cur][nt]);
    }
#undef LOAD_FRAGS

    // --- epilogue: scatter into g_Y[b][f][o][re,im] ---
    int g = lane >> 2, tg = lane & 3;
#pragma unroll
    for (int mt = 0; mt < 2; mt++) {
        int brow = bt * 64 + wm * 32 + mt * 16 + g;
        float* base0 = g_Y + ((size_t)brow * NF + f) * 128;
        float* base1 = g_Y + ((size_t)(brow + 8) * NF + f) * 128;
#pragma unroll
        for (int nt = 0; nt < 4; nt++) {
            int n = wn * 32 + nt * 8 + 2 * tg;
            int o = n & 63, comp = n >> 6;
            int d = o * 2 + comp;
            base0[d]     = acc[mt][nt][0];
            base0[d + 2] = acc[mt][nt][1];
            base1[d]     = acc[mt][nt][2];
            base1[d + 2] = acc[mt][nt][3];
        }
    }
}

// ---------------- K3: Hermitian IFFT, 2 real output blocks per FFT ------------
__global__ void __launch_bounds__(512) ifft_kernel(float* __restrict__ out) {
    extern __shared__ float sm[];
    float* sYr = sm;                  // [64][65]
    float* sYi = sYr + 64 * 65;
    float* st  = sYi + 64 * 65;       // [16][256]
    float* twc = st + 16 * 256;
    float* tws = twc + 64;
    int b = blockIdx.x, tid = threadIdx.x;
    if (tid < 64) {
        float ang = -6.2831853071795864769f * (float)tid / 128.0f;
        twc[tid] = cosf(ang);
        tws[tid] = sinf(ang);
    }
    const float2* gy = (const float2*)(g_Y + (size_t)b * (NF * KOUT * 2));
    for (int i = tid; i < NF * KOUT; i += 512) {
        int f = i >> 6, o = i & 63;
        float2 v = gy[i];
        sYr[o * 65 + f] = v.x;
        sYi[o * 65 + f] = v.y;
    }
    __syncthreads();

    int warp = tid >> 5, lane = tid & 31;
    float* stw = st + warp * 256;
    for (int q = 0; q < 2; q++) {
        int o = warp * 4 + q * 2;
        float zr[4], zi[4];
#pragma unroll
        for (int r = 0; r < 4; r++) {
            int k = r * 32 + lane;
            if (k <= 64) {
                float a  = sYr[o * 65 + k],       bb = sYi[o * 65 + k];
                float c  = sYr[(o + 1) * 65 + k], d  = sYi[(o + 1) * 65 + k];
                zr[r] = a - d;  zi[r] = bb + c;
            } else {
                int k2 = 128 - k;
                float a  = sYr[o * 65 + k2],       bb = sYi[o * 65 + k2];
                float c  = sYr[(o + 1) * 65 + k2], d  = sYi[(o + 1) * 65 + k2];
                zr[r] = a + d;  zi[r] = c - bb;
            }
            zi[r] = -zi[r];
        }
        fft128(zr, zi, twc, tws, lane);
#pragma unroll
        for (int r = 0; r < 4; r++) {
            int n = r * 32 + lane;
            int tp = __brev((unsigned)n) >> 25;
            stw[tp]       = zr[r] * (1.0f / 128.0f);
            stw[128 + tp] = zi[r] * (-1.0f / 128.0f);
        }
        __syncwarp();
        float* dst = out + (size_t)b * DOUT + o * 128;
#pragma unroll
        for (int r = 0; r < 8; r++)
            dst[r * 32 + lane] = stw[r * 32 + lane];
        __syncwarp();
    }
}

// ---------------- launch ------------------------------------------------------
extern "C" void kernel_launch(void* const* d_in, const int* in_sizes, int n_in,
                              void* d_out, int out_size) {
    const float* x = (const float*)d_in[0];   // (4096, 8192)
    const float* W = (const float*)d_in[1];   // (64, 64, 128)
    const float* D = (const float*)d_in[2];   // (8192,)
    float* out = (float*)d_out;               // (4096, 8192)
    (void)in_sizes; (void)n_in; (void)out_size;

    const int smem_x = (2 * 128 * 33 + 128) * 4;                  // 34304 B
    const int smem_g = 104448;                                    // A+B hi/lo tiles
    const int smem_i = (2 * 64 * 65 + 16 * 256 + 128) * 4;        // 50176 B
    cudaFuncSetAttribute(xfft_kernel,      cudaFuncAttributeMaxDynamicSharedMemorySize, smem_x);
    cudaFuncSetAttribute(cgemm_mma_kernel, cudaFuncAttributeMaxDynamicSharedMemorySize, smem_g);
    cudaFuncSetAttribute(ifft_kernel,      cudaFuncAttributeMaxDynamicSharedMemorySize, smem_i);

    wfft_kernel<<<KOUT * KIN, 128>>>(W);
    bprep_kernel<<<NF, 256>>>();
    xfft_kernel<<<BATCH, 512, smem_x>>>(x, D);
    cgemm_mma_kernel<<<dim3(BATCH / 64, NF), 256, smem_g>>>();
    ifft_kernel<<<BATCH, 512, smem_i>>>(out);
}

// round 12
// speedup vs baseline: 1.3294x; 1.3294x over previous
#include <cuda_runtime.h>
#include <cuda_bf16.h>
#include <cstdint>
#include <cstddef>

#define BATCH 4096
#define DIN   8192
#define DOUT  8192
#define KIN   64
#define KOUT  64
#define NF    65     // rfft bins of 128

#define GEMM_GRID 296            // 2 per SM on 148 SMs
#define TILES_PER_F 128          // 4096 rows / 32
#define TOT_TILES (NF * TILES_PER_F)

// ---------------- scratch (static device globals; no allocation) -------------
// X in bf16 hi/lo, ldmatrix-ready: row = batch row, 128 bf16 = [Xr(64) | Xi(64)]
__device__ __align__(16) __nv_bfloat16 g_Xhi[NF][(size_t)BATCH * 128];
__device__ __align__(16) __nv_bfloat16 g_Xlo[NF][(size_t)BATCH * 128];
__device__ float g_Wre[NF][KIN * KOUT];              // [f][j*64+o] = Re conj(fft W)
__device__ float g_Wim[NF][KIN * KOUT];              // [f][j*64+o] = Im conj(fft W)
__device__ float g_Y[(size_t)BATCH * NF * KOUT * 2]; // [b][f][o][re,im]
// B tiles, row-major [n][k] bf16 hi/lo per frequency (128x128 each)
__device__ __align__(16) __nv_bfloat16 g_Bhi[NF][128 * 128];
__device__ __align__(16) __nv_bfloat16 g_Blo[NF][128 * 128];

__device__ __forceinline__ uint32_t smem_to_u32(const void* p) {
    uint32_t a;
    asm("{ .reg .u64 t; cvta.to.shared.u64 t, %1; cvt.u32.u64 %0, t; }"
        : "=r"(a) : "l"(p));
    return a;
}
#define LDMATRIX_X4(r0, r1, r2, r3, addr) \
    asm volatile("ldmatrix.sync.aligned.m8n8.x4.shared.b16 {%0,%1,%2,%3}, [%4];" \
        : "=r"(r0), "=r"(r1), "=r"(r2), "=r"(r3) : "r"(addr))
#define MMA_BF16(c, a, b) \
    asm("mma.sync.aligned.m16n8k16.row.col.f32.bf16.bf16.f32 " \
        "{%0,%1,%2,%3}, {%4,%5,%6,%7}, {%8,%9}, {%0,%1,%2,%3};" \
        : "+f"((c)[0]), "+f"((c)[1]), "+f"((c)[2]), "+f"((c)[3]) \
        : "r"((a)[0]), "r"((a)[1]), "r"((a)[2]), "r"((a)[3]), \
          "r"((b)[0]), "r"((b)[1]))
#define CP_ASYNC16(dst, src) \
    asm volatile("cp.async.cg.shared.global [%0], [%1], 16;" \
        :: "r"(dst), "l"(src) : "memory")
#define CP_COMMIT() asm volatile("cp.async.commit_group;" ::: "memory")
#define CP_WAIT0()  asm volatile("cp.async.wait_group 0;" ::: "memory")

// ---------------- warp-level 128-pt radix-2 DIF FFT --------------------------
__device__ __forceinline__ void fft128(float xr[4], float xi[4],
                                       const float* __restrict__ twc,
                                       const float* __restrict__ tws,
                                       int lane) {
#pragma unroll
    for (int r = 0; r < 2; r++) {
        int i = r * 32 + lane;
        float ar = xr[r], ai = xi[r], br = xr[r + 2], bi = xi[r + 2];
        xr[r] = ar + br; xi[r] = ai + bi;
        float dr = ar - br, di = ai - bi;
        float c = twc[i], s = tws[i];
        xr[r + 2] = dr * c - di * s;
        xi[r + 2] = dr * s + di * c;
    }
    {
        float c = twc[2 * lane], s = tws[2 * lane];
#pragma unroll
        for (int p = 0; p < 2; p++) {
            int a = 2 * p, bq = 2 * p + 1;
            float ar = xr[a], ai = xi[a], br = xr[bq], bi = xi[bq];
            xr[a] = ar + br; xi[a] = ai + bi;
            float dr = ar - br, di = ai - bi;
            xr[bq] = dr * c - di * s;
            xi[bq] = dr * s + di * c;
        }
    }
#pragma unroll
    for (int h = 16; h >= 1; h >>= 1) {
        int m = (lane & (h - 1)) * (64 / h);
        float c = twc[m], s = tws[m];
        bool upper = (lane & h) != 0;
#pragma unroll
        for (int r = 0; r < 4; r++) {
            float pr = __shfl_xor_sync(0xffffffffu, xr[r], h);
            float pi = __shfl_xor_sync(0xffffffffu, xi[r], h);
            float ur = upper ? pr : xr[r];
            float ui = upper ? pi : xi[r];
            float vr = upper ? xr[r] : pr;
            float vi = upper ? xi[r] : pi;
            if (!upper) { xr[r] = ur + vr; xi[r] = ui + vi; }
            else {
                float dr = ur - vr, di = ui - vi;
                xr[r] = dr * c - di * s;
                xi[r] = dr * s + di * c;
            }
        }
    }
}

// ---------------- K0: conj(FFT) of weight first-rows -------------------------
__global__ void wfft_kernel(const float* __restrict__ W) {
    __shared__ float sw[128];
    __shared__ float tc[128];
    __shared__ float ts[128];
    int oj = blockIdx.x;
    int t = threadIdx.x;
    sw[t] = W[oj * 128 + t];
    float ang = 6.2831853071795864769f * (float)t / 128.0f;  // +sin => conj
    tc[t] = cosf(ang);
    ts[t] = sinf(ang);
    __syncthreads();
    if (t < NF) {
        float ar = 0.f, ai = 0.f;
#pragma unroll 8
        for (int u = 0; u < 128; u++) {
            int p = (t * u) & 127;
            ar = fmaf(sw[u], tc[p], ar);
            ai = fmaf(sw[u], ts[p], ai);
        }
        int o = oj >> 6, j = oj & 63;
        g_Wre[t][j * 64 + o] = ar;
        g_Wim[t][j * 64 + o] = ai;
    }
}

// ---------------- K0b: build B tiles (bf16 hi/lo, row-major [n][k]) ----------
__global__ void bprep_kernel() {
    int f = blockIdx.x;
    for (int i = threadIdx.x; i < 128 * 128; i += blockDim.x) {
        int n = i >> 7, k = i & 127;
        int o = n & 63, j = k & 63;
        float wr = g_Wre[f][j * 64 + o];
        float wi = g_Wim[f][j * 64 + o];
        float v = (n < 64) ? ((k < 64) ? wr : -wi)
                           : ((k < 64) ? wi :  wr);
        __nv_bfloat16 h = __float2bfloat16(v);
        float lo = v - __bfloat162float(h);
        g_Bhi[f][i] = h;
        g_Blo[f][i] = __float2bfloat16(lo);
    }
}

// ---------------- K1: FFT of x blocks; emit bf16 hi/lo X ----------------------
__global__ void __launch_bounds__(512) xfft_kernel(const float* __restrict__ x,
                                                   const float* __restrict__ D) {
    extern __shared__ float sm[];
    float* sZr = sm;                 // [128][33]
    float* sZi = sZr + 128 * 33;
    float* twc = sZi + 128 * 33;
    float* tws = twc + 64;
    int b = blockIdx.x, tid = threadIdx.x;
    if (tid < 64) {
        float ang = -6.2831853071795864769f * (float)tid / 128.0f;
        twc[tid] = cosf(ang);
        tws[tid] = sinf(ang);
    }
    __syncthreads();
    int warp = tid >> 5, lane = tid & 31;
    const float* xb = x + (size_t)b * DIN;
    for (int pp = 0; pp < 2; pp++) {
        int p = warp * 2 + pp;
        float xr[4], xi[4];
#pragma unroll
        for (int r = 0; r < 4; r++) {
            int n = r * 32 + lane;
            int iu = (2 * p) * 128 + n;
            int iv = iu + 128;
            xr[r] = xb[iu] * D[iu];
            xi[r] = xb[iv] * D[iv];
        }
        fft128(xr, xi, twc, tws, lane);
#pragma unroll
        for (int r = 0; r < 4; r++) {
            int n = r * 32 + lane;
            sZr[n * 33 + p] = xr[r];
            sZi[n * 33 + p] = xi[r];
        }
    }
    __syncthreads();
    size_t rb = (size_t)b * 128;
    for (int i = tid; i < NF * KIN; i += 512) {
        int f = i >> 6, j = i & 63;
        int p = j >> 1, v = j & 1;
        int g = (128 - f) & 127;
        int sf = __brev((unsigned)f) >> 25;
        int sg = __brev((unsigned)g) >> 25;
        float zr1 = sZr[sf * 33 + p], zi1 = sZi[sf * 33 + p];
        float zr2 = sZr[sg * 33 + p], zi2 = sZi[sg * 33 + p];
        float outr, outi;
        if (v == 0) { outr = 0.5f * (zr1 + zr2); outi = 0.5f * (zi1 - zi2); }
        else        { outr = 0.5f * (zi1 + zi2); outi = 0.5f * (zr2 - zr1); }
        __nv_bfloat16 hr = __float2bfloat16(outr);
        __nv_bfloat16 hi = __float2bfloat16(outi);
        g_Xhi[f][rb + j]      = hr;
        g_Xhi[f][rb + 64 + j] = hi;
        g_Xlo[f][rb + j]      = __float2bfloat16(outr - __bfloat162float(hr));
        g_Xlo[f][rb + 64 + j] = __float2bfloat16(outi - __bfloat162float(hi));
    }
}

// ---------------- K2: persistent per-f GEMM, cp.async pipelined ---------------
// 296 CTAs x 256 thr (8 warps, 2M x 4N, warp tile 16x32). Each CTA owns a
// contiguous range of (f, 32-row) tiles; B resident per f; A double-buffered.
// SMEM (PITCH 272): Abuf0 hi@0 lo@8704; Abuf1 hi@17408 lo@26112;
//                   Bh@34816 (128x272); Bl@69632.  Total 104448 -> 2 CTAs/SM.
__global__ void __launch_bounds__(256, 2) cgemm_mma_kernel() {
    extern __shared__ char smem[];
    const int PITCH = 272;
    const uint32_t BHOFF = 34816, BLOFF = 69632;
    int tid = threadIdx.x;
    uint32_t sA = smem_to_u32(smem);

    int cta = blockIdx.x;
    int u0 = (int)(((long long)TOT_TILES * cta) / GEMM_GRID);
    int u1 = (int)(((long long)TOT_TILES * (cta + 1)) / GEMM_GRID);

    int lane = tid & 31, wid = tid >> 5;
    int wm = wid >> 2, wn = wid & 3;          // warp tile: M 16 x N 32
    int r = lane & 7, ti = lane >> 3;

    uint32_t aRel = (uint32_t)((wm * 16 + r + 8 * (ti & 1)) * PITCH
                               + (ti >> 1) * 16);
    uint32_t bBase0 = sA + BHOFF + (uint32_t)((wn * 32 + r + 8 * (ti >> 1)) * PITCH
                                              + (ti & 1) * 16);
    uint32_t bBase1 = bBase0 + 16 * PITCH;

    // ---- A tile stage: 1024 x 16B chunks (hi 512 + lo 512), 4 per thread ----
#define STAGE_A(buf_, u_) do {                                                  \
        int f_ = (u_) >> 7, t_ = (u_) & 127;                                    \
        const __nv_bfloat16* sh_ = g_Xhi[f_] + (size_t)(t_) * 32 * 128;         \
        const __nv_bfloat16* sl_ = g_Xlo[f_] + (size_t)(t_) * 32 * 128;         \
        _Pragma("unroll")                                                       \
        for (int s_ = 0; s_ < 4; s_++) {                                        \
            int ch_ = tid + s_ * 256;                                           \
            int comp_ = ch_ >> 9;                                               \
            int rm_ = (ch_ >> 4) & 31;                                          \
            int c_ = ch_ & 15;                                                  \
            uint32_t dst_ = sA + (buf_) * 17408 + comp_ * 8704                  \
                            + rm_ * PITCH + c_ * 16;                            \
            const __nv_bfloat16* src_ = (comp_ ? sl_ : sh_) + rm_ * 128 + c_ * 8;\
            CP_ASYNC16(dst_, src_);                                             \
        }                                                                       \
        CP_COMMIT();                                                            \
    } while (0)

    int fcur = -1;
    if (u0 < u1) STAGE_A(0, u0);

    for (int u = u0; u < u1; u++) {
        int buf = (u - u0) & 1;
        int f = u >> 7, t = u & 127;
        CP_WAIT0();
        __syncthreads();
        if (f != fcur) {                      // (re)load B for this frequency
            const uint4* bh = (const uint4*)g_Bhi[f];
            const uint4* bl = (const uint4*)g_Blo[f];
            for (int idx = tid; idx < 2048; idx += 256) {
                int n = idx >> 4, c = idx & 15;
                *(uint4*)(smem + BHOFF + n * PITCH + c * 16) = bh[idx];
                *(uint4*)(smem + BLOFF + n * PITCH + c * 16) = bl[idx];
            }
            fcur = f;
            __syncthreads();
        }
        if (u + 1 < u1) STAGE_A(buf ^ 1, u + 1);   // prefetch next tile

        uint32_t aBase = sA + buf * 17408 + aRel;

        float acc[4][4];
#pragma unroll
        for (int nt = 0; nt < 4; nt++)
#pragma unroll
            for (int q = 0; q < 4; q++) acc[nt][q] = 0.f;

        uint32_t af[2][4];
        uint32_t bfr[2][4][2];
#define LOAD_FRAGS(pb, it_) do {                                                \
            const int s_ = (it_) >> 3;                                          \
            const uint32_t aO = (s_ == 2) ? 8704u : 0u;                         \
            const uint32_t bO = (s_ == 1) ? (BLOFF - BHOFF) : 0u;               \
            const uint32_t ka = ((it_) & 7) * 32;                               \
            LDMATRIX_X4(af[pb][0], af[pb][1], af[pb][2], af[pb][3],             \
                        aBase + aO + ka);                                       \
            LDMATRIX_X4(bfr[pb][0][0], bfr[pb][0][1], bfr[pb][1][0],            \
                        bfr[pb][1][1], bBase0 + bO + ka);                       \
            LDMATRIX_X4(bfr[pb][2][0], bfr[pb][2][1], bfr[pb][3][0],            \
                        bfr[pb][3][1], bBase1 + bO + ka);                       \
        } while (0)

        LOAD_FRAGS(0, 0);
#pragma unroll
        for (int it = 0; it < 24; it++) {
            const int cur = it & 1;
            if (it + 1 < 24) LOAD_FRAGS(cur ^ 1, it + 1);
#pragma unroll
            for (int nt = 0; nt < 4; nt++)
                MMA_BF16(acc[nt], af[cur], bfr[cur][nt]);
        }
#undef LOAD_FRAGS

        // epilogue: scatter into g_Y[b][f][o][re,im]
        int g = lane >> 2, tg = lane & 3;
        int brow = t * 32 + wm * 16 + g;
        float* base0 = g_Y + ((size_t)brow * NF + f) * 128;
        float* base1 = g_Y + ((size_t)(brow + 8) * NF + f) * 128;
#pragma unroll
        for (int nt = 0; nt < 4; nt++) {
            int n = wn * 32 + nt * 8 + 2 * tg;
            int o = n & 63, comp = n >> 6;
            int d = o * 2 + comp;
            base0[d]     = acc[nt][0];
            base0[d + 2] = acc[nt][1];
            base1[d]     = acc[nt][2];
            base1[d + 2] = acc[nt][3];
        }
    }
#undef STAGE_A
}

// ---------------- K3: Hermitian IFFT, 2 real output blocks per FFT ------------
__global__ void __launch_bounds__(512) ifft_kernel(float* __restrict__ out) {
    extern __shared__ float sm[];
    float* sYr = sm;                  // [64][65]
    float* sYi = sYr + 64 * 65;
    float* st  = sYi + 64 * 65;       // [16][256]
    float* twc = st + 16 * 256;
    float* tws = twc + 64;
    int b = blockIdx.x, tid = threadIdx.x;
    if (tid < 64) {
        float ang = -6.2831853071795864769f * (float)tid / 128.0f;
        twc[tid] = cosf(ang);
        tws[tid] = sinf(ang);
    }
    const float2* gy = (const float2*)(g_Y + (size_t)b * (NF * KOUT * 2));
    for (int i = tid; i < NF * KOUT; i += 512) {
        int f = i >> 6, o = i & 63;
        float2 v = gy[i];
        sYr[o * 65 + f] = v.x;
        sYi[o * 65 + f] = v.y;
    }
    __syncthreads();

    int warp = tid >> 5, lane = tid & 31;
    float* stw = st + warp * 256;
    for (int q = 0; q < 2; q++) {
        int o = warp * 4 + q * 2;
        float zr[4], zi[4];
#pragma unroll
        for (int r = 0; r < 4; r++) {
            int k = r * 32 + lane;
            if (k <= 64) {
                float a  = sYr[o * 65 + k],       bb = sYi[o * 65 + k];
                float c  = sYr[(o + 1) * 65 + k], d  = sYi[(o + 1) * 65 + k];
                zr[r] = a - d;  zi[r] = bb + c;
            } else {
                int k2 = 128 - k;
                float a  = sYr[o * 65 + k2],       bb = sYi[o * 65 + k2];
                float c  = sYr[(o + 1) * 65 + k2], d  = sYi[(o + 1) * 65 + k2];
                zr[r] = a + d;  zi[r] = c - bb;
            }
            zi[r] = -zi[r];
        }
        fft128(zr, zi, twc, tws, lane);
#pragma unroll
        for (int r = 0; r < 4; r++) {
            int n = r * 32 + lane;
            int tp = __brev((unsigned)n) >> 25;
            stw[tp]       = zr[r] * (1.0f / 128.0f);
            stw[128 + tp] = zi[r] * (-1.0f / 128.0f);
        }
        __syncwarp();
        float* dst = out + (size_t)b * DOUT + o * 128;
#pragma unroll
        for (int r = 0; r < 8; r++)
            dst[r * 32 + lane] = stw[r * 32 + lane];
        __syncwarp();
    }
}

// ---------------- launch ------------------------------------------------------
extern "C" void kernel_launch(void* const* d_in, const int* in_sizes, int n_in,
                              void* d_out, int out_size) {
    const float* x = (const float*)d_in[0];   // (4096, 8192)
    const float* W = (const float*)d_in[1];   // (64, 64, 128)
    const float* D = (const float*)d_in[2];   // (8192,)
    float* out = (float*)d_out;               // (4096, 8192)
    (void)in_sizes; (void)n_in; (void)out_size;

    const int smem_x = (2 * 128 * 33 + 128) * 4;                  // 34304 B
    const int smem_g = 104448;                                    // A bufs + B
    const int smem_i = (2 * 64 * 65 + 16 * 256 + 128) * 4;        // 50176 B
    cudaFuncSetAttribute(xfft_kernel,      cudaFuncAttributeMaxDynamicSharedMemorySize, smem_x);
    cudaFuncSetAttribute(cgemm_mma_kernel, cudaFuncAttributeMaxDynamicSharedMemorySize, smem_g);
    cudaFuncSetAttribute(ifft_kernel,      cudaFuncAttributeMaxDynamicSharedMemorySize, smem_i);

    wfft_kernel<<<KOUT * KIN, 128>>>(W);
    bprep_kernel<<<NF, 256>>>();
    xfft_kernel<<<BATCH, 512, smem_x>>>(x, D);
    cgemm_mma_kernel<<<GEMM_GRID, 256, smem_g>>>();
    ifft_kernel<<<BATCH, 512, smem_i>>>(out);
}